// round 12
// baseline (speedup 1.0000x reference)
#include <cuda_runtime.h>
#include <cuda_fp16.h>
#include <cstdint>

// SGNS loss, fp16-everything scheme (R10 structure + MLP-4 conversion):
//  K1a/K1b: convert emb and out_w fp32->fp16, 16 elems/thread
//           (4 independent LDG.128 = MLP 4, 2 plain STG.128).
//  K2: main SGNS pass (proven): uint4-per-lane fp16 gathers (one 128B line
//      per LDG), distributed index fetch, parallel log-sigmoid epilogue,
//      __stwt output. Steady-state main pass sits at the LTS service cap
//      (~470MB / ~31us); conversion is the remaining wall-time component.

#define D 128
#define KNEG 5
#define LPP 8          // lanes per pair
#define VMAX 100000

// fp16 mirrors: V*D halves = 25.6MB each
__device__ uint4 g_w_h[(size_t)VMAX * D / 8];
__device__ uint4 g_e_h[(size_t)VMAX * D / 8];

__device__ __forceinline__ float log_sigmoid(float x) {
    return fminf(x, 0.0f) - log1pf(__expf(-fabsf(x)));
}

__device__ __forceinline__ float4 ldg_f4_hint(const void* p, uint64_t pol) {
    float4 v;
    asm volatile("ld.global.nc.L2::cache_hint.v4.f32 {%0,%1,%2,%3}, [%4], %5;"
                 : "=f"(v.x), "=f"(v.y), "=f"(v.z), "=f"(v.w)
                 : "l"(p), "l"(pol));
    return v;
}

__device__ __forceinline__ uint4 ldg_u4_hint(const void* p, uint64_t pol) {
    uint4 v;
    asm volatile("ld.global.nc.L2::cache_hint.v4.b32 {%0,%1,%2,%3}, [%4], %5;"
                 : "=r"(v.x), "=r"(v.y), "=r"(v.z), "=r"(v.w)
                 : "l"(p), "l"(pol));
    return v;
}

__device__ __forceinline__ uint4 pack8(float4 a, float4 b) {
    uint4 o;
    __half2 h;
    h = __floats2half2_rn(a.x, a.y); o.x = *reinterpret_cast<const uint32_t*>(&h);
    h = __floats2half2_rn(a.z, a.w); o.y = *reinterpret_cast<const uint32_t*>(&h);
    h = __floats2half2_rn(b.x, b.y); o.z = *reinterpret_cast<const uint32_t*>(&h);
    h = __floats2half2_rn(b.z, b.w); o.w = *reinterpret_cast<const uint32_t*>(&h);
    return o;
}

// K1: fp32 -> fp16 table conversion, 16 elements per thread (MLP=4)
__global__ void __launch_bounds__(256) convert_kernel(
    const float* __restrict__ src, uint4* __restrict__ dst, int n_elem)
{
    uint64_t pol_first;
    asm("createpolicy.fractional.L2::evict_first.b64 %0, 1.0;" : "=l"(pol_first));
    int i = (blockIdx.x * blockDim.x + threadIdx.x) * 16;
    if (i >= n_elem) return;
    float4 a0 = ldg_f4_hint(src + i,      pol_first);
    float4 a1 = ldg_f4_hint(src + i + 4,  pol_first);
    float4 a2 = ldg_f4_hint(src + i + 8,  pol_first);
    float4 a3 = ldg_f4_hint(src + i + 12, pol_first);
    dst[(i >> 3)]     = pack8(a0, a1);   // plain stores: write-allocate into L2
    dst[(i >> 3) + 1] = pack8(a2, a3);
}

// K2: main SGNS pass (all-fp16 gathers, fp32 accumulate)
__global__ void __launch_bounds__(256) sgns_loss_kernel(
    const int* __restrict__ tgt_ids,
    const int* __restrict__ ctx_ids,
    const int* __restrict__ neg_ids,
    float*     __restrict__ out,
    int N)
{
    const int tid  = blockIdx.x * blockDim.x + threadIdx.x;
    const int pair = tid >> 3;
    const int lane = threadIdx.x & (LPP - 1);
    if (pair >= N) return;

    uint64_t pol_last;
    asm("createpolicy.fractional.L2::evict_last.b64 %0, 1.0;" : "=l"(pol_last));

    const unsigned gmask = 0xFFu << ((threadIdx.x & 31) & ~(LPP - 1));

    // Distributed index fetch: slot 0=tgt, 1=ctx, 2..6=neg[0..4]
    int myidx = 0;
    if (lane == 0)      myidx = __ldg(tgt_ids + pair);
    else if (lane == 1) myidx = __ldg(ctx_ids + pair);
    else if (lane < 7)  myidx = __ldg(neg_ids + pair * KNEG + (lane - 2));

    // fp16 rows are 256B
    const unsigned t_off = (unsigned)__shfl_sync(gmask, myidx, 0, LPP) << 8;
    unsigned roff[1 + KNEG];
#pragma unroll
    for (int j = 0; j < 1 + KNEG; j++)
        roff[j] = (unsigned)__shfl_sync(gmask, myidx, 1 + j, LPP) << 8;

    const char* e_b = reinterpret_cast<const char*>(g_e_h);
    const char* w_b = reinterpret_cast<const char*>(g_w_h);
    const unsigned lane16 = (unsigned)lane * 16u;  // uint4 slot in the 128B line

    // input row: chunk i (i=0,1) = uint4 at byte 16l + 128i -> dims 8l+64i..+7
    float ivf[16];
#pragma unroll
    for (int i = 0; i < 2; i++) {
        uint4 u = ldg_u4_hint(e_b + t_off + lane16 + 128u * i, pol_last);
        const __half2* h = reinterpret_cast<const __half2*>(&u);
#pragma unroll
        for (int q = 0; q < 4; q++) {
            float2 f = __half22float2(h[q]);
            ivf[i * 8 + q * 2 + 0] = f.x;
            ivf[i * 8 + q * 2 + 1] = f.y;
        }
    }

    // double-buffered walk over the 6 fp16 w rows
    uint4 cur[2], nxt[2];
#pragma unroll
    for (int i = 0; i < 2; i++)
        cur[i] = ldg_u4_hint(w_b + roff[0] + lane16 + 128u * i, pol_last);

    float s[1 + KNEG];
#pragma unroll
    for (int j = 0; j < 1 + KNEG; j++) {
        if (j < KNEG) {
#pragma unroll
            for (int i = 0; i < 2; i++)
                nxt[i] = ldg_u4_hint(w_b + roff[j + 1] + lane16 + 128u * i, pol_last);
        }
        float acc = 0.f;
#pragma unroll
        for (int i = 0; i < 2; i++) {
            const __half2* h = reinterpret_cast<const __half2*>(&cur[i]);
#pragma unroll
            for (int q = 0; q < 4; q++) {
                float2 f = __half22float2(h[q]);
                acc = fmaf(ivf[i * 8 + q * 2 + 0], f.x, acc);
                acc = fmaf(ivf[i * 8 + q * 2 + 1], f.y, acc);
            }
        }
        s[j] = acc;
        if (j < KNEG) {
            cur[0] = nxt[0];
            cur[1] = nxt[1];
        }
    }

    // 3-stage butterfly: all lanes end with all 6 sums
#pragma unroll
    for (int j = 0; j < 1 + KNEG; j++) {
#pragma unroll
        for (int off = LPP / 2; off > 0; off >>= 1)
            s[j] += __shfl_xor_sync(gmask, s[j], off, LPP);
    }

    // Parallel epilogue: lanes 0..5 each evaluate one log-sigmoid term
    float x = (lane == 0) ? s[0] : -s[lane < 6 ? lane : 0];
    float term = log_sigmoid(x);
    if (lane >= 6) term = 0.f;
#pragma unroll
    for (int off = LPP / 2; off > 0; off >>= 1)
        term += __shfl_xor_sync(gmask, term, off, LPP);

    if (lane == 0)
        __stwt(out + pair, -term);
}

extern "C" void kernel_launch(void* const* d_in, const int* in_sizes, int n_in,
                              void* d_out, int out_size) {
    const float* emb     = (const float*)d_in[0];
    const float* out_w   = (const float*)d_in[1];
    const int*   tgt_ids = (const int*)d_in[2];
    const int*   ctx_ids = (const int*)d_in[3];
    const int*   neg_ids = (const int*)d_in[4];
    float*       out     = (float*)d_out;

    const int n_e = in_sizes[0];              // V * D elements (emb)
    const int n_w = in_sizes[1];              // V * D elements (out_w)
    const int N   = in_sizes[2];              // number of pairs

    uint4 *d_e_h, *d_w_h;
    cudaGetSymbolAddress((void**)&d_e_h, g_e_h);
    cudaGetSymbolAddress((void**)&d_w_h, g_w_h);

    // K1: convert both tables -> fp16 (16 elems/thread, MLP=4)
    {
        const int threads = 256;
        convert_kernel<<<(n_e / 16 + threads - 1) / threads, threads>>>(emb, d_e_h, n_e);
        convert_kernel<<<(n_w / 16 + threads - 1) / threads, threads>>>(out_w, d_w_h, n_w);
    }

    // K2: main pass
    {
        const int threads = 256;               // 32 pairs per block
        const int pairs_per_block = threads / LPP;
        const int blocks = (N + pairs_per_block - 1) / pairs_per_block;
        sgns_loss_kernel<<<blocks, threads>>>(tgt_ids, ctx_ids, neg_ids, out, N);
    }
}

// round 13
// speedup vs baseline: 1.1191x; 1.1191x over previous
#include <cuda_runtime.h>
#include <cuda_fp16.h>
#include <cstdint>

// SGNS loss, hybrid precision (cost-ledger optimized):
//  - out_w -> fp16 scratch once per launch (12.5us; saves ~27us of main-pass
//    LTS traffic). emb stays fp32: converting it costs 12.5us but saves only
//    ~4.5us -> net loss, so no emb conversion (R12 finding).
//  K2 main pass: emb fp32 via 4x LDG.128/pair, w fp16 via 2x LDG.128/pair
//  (every load = one full 128B line). w scratch pinned with evict_last
//  (25.6MB); emb (51.2MB) default LRU, co-resident. __stwt output.
//  Distributed index fetch + parallel log-sigmoid epilogue (proven).

#define D 128
#define KNEG 5
#define LPP 8          // lanes per pair
#define VMAX 100000

// fp16 mirror of out_w: V*D halves = 25.6MB
__device__ uint4 g_w_h[(size_t)VMAX * D / 8];

__device__ __forceinline__ float log_sigmoid(float x) {
    return fminf(x, 0.0f) - log1pf(__expf(-fabsf(x)));
}

__device__ __forceinline__ float4 ldg_f4_hint(const void* p, uint64_t pol) {
    float4 v;
    asm volatile("ld.global.nc.L2::cache_hint.v4.f32 {%0,%1,%2,%3}, [%4], %5;"
                 : "=f"(v.x), "=f"(v.y), "=f"(v.z), "=f"(v.w)
                 : "l"(p), "l"(pol));
    return v;
}

__device__ __forceinline__ uint4 ldg_u4_hint(const void* p, uint64_t pol) {
    uint4 v;
    asm volatile("ld.global.nc.L2::cache_hint.v4.b32 {%0,%1,%2,%3}, [%4], %5;"
                 : "=r"(v.x), "=r"(v.y), "=r"(v.z), "=r"(v.w)
                 : "l"(p), "l"(pol));
    return v;
}

__device__ __forceinline__ uint4 pack8(float4 a, float4 b) {
    uint4 o;
    __half2 h;
    h = __floats2half2_rn(a.x, a.y); o.x = *reinterpret_cast<const uint32_t*>(&h);
    h = __floats2half2_rn(a.z, a.w); o.y = *reinterpret_cast<const uint32_t*>(&h);
    h = __floats2half2_rn(b.x, b.y); o.z = *reinterpret_cast<const uint32_t*>(&h);
    h = __floats2half2_rn(b.z, b.w); o.w = *reinterpret_cast<const uint32_t*>(&h);
    return o;
}

// K1: fp32 -> fp16 conversion of out_w, 8 elements per thread (R10 champion)
__global__ void __launch_bounds__(256) convert_w_kernel(
    const float* __restrict__ src, int n_elem)
{
    uint64_t pol_first;
    asm("createpolicy.fractional.L2::evict_first.b64 %0, 1.0;" : "=l"(pol_first));
    int i = (blockIdx.x * blockDim.x + threadIdx.x) * 8;
    if (i >= n_elem) return;
    float4 a = ldg_f4_hint(src + i,     pol_first);
    float4 b = ldg_f4_hint(src + i + 4, pol_first);
    g_w_h[i >> 3] = pack8(a, b);   // plain store: write-allocate into L2
}

// K2: main SGNS pass (fp32 emb gathers, fp16 w gathers, fp32 accumulate)
__global__ void __launch_bounds__(256) sgns_loss_kernel(
    const float* __restrict__ emb,
    const int*   __restrict__ tgt_ids,
    const int*   __restrict__ ctx_ids,
    const int*   __restrict__ neg_ids,
    float*       __restrict__ out,
    int N)
{
    const int tid  = blockIdx.x * blockDim.x + threadIdx.x;
    const int pair = tid >> 3;
    const int lane = threadIdx.x & (LPP - 1);
    if (pair >= N) return;

    uint64_t pol_last;
    asm("createpolicy.fractional.L2::evict_last.b64 %0, 1.0;" : "=l"(pol_last));

    const unsigned gmask = 0xFFu << ((threadIdx.x & 31) & ~(LPP - 1));

    // Distributed index fetch: slot 0=tgt, 1=ctx, 2..6=neg[0..4]
    int myidx = 0;
    if (lane == 0)      myidx = __ldg(tgt_ids + pair);
    else if (lane == 1) myidx = __ldg(ctx_ids + pair);
    else if (lane < 7)  myidx = __ldg(neg_ids + pair * KNEG + (lane - 2));

    const unsigned t_off = (unsigned)__shfl_sync(gmask, myidx, 0, LPP) << 9;  // fp32 row: 512B
    unsigned roff[1 + KNEG];                                                  // fp16 row: 256B
#pragma unroll
    for (int j = 0; j < 1 + KNEG; j++)
        roff[j] = (unsigned)__shfl_sync(gmask, myidx, 1 + j, LPP) << 8;

    const char* e_b = reinterpret_cast<const char*>(emb);
    const char* w_b = reinterpret_cast<const char*>(g_w_h);
    const unsigned lane16 = (unsigned)lane * 16u;

    // input row (fp32): chunk i (i=0..3) = float4 at byte 16l + 128i
    //   -> dims 4l + 32i .. 4l + 32i + 3
    float4 iv[4];
#pragma unroll
    for (int i = 0; i < 4; i++)
        iv[i] = __ldg(reinterpret_cast<const float4*>(e_b + t_off + lane16 + 128u * i));

    // w rows (fp16): chunk i (i=0,1) = uint4 at byte 16l + 128i
    //   -> dims 8l + 64i .. 8l + 64i + 7
    // Map to iv: dim d = 8l+64i+2q+r lives in iv[(d/32)].{d%4} with lane match:
    //   8l+64i+k (k=0..7) -> for k=0..3: iv-chunk (2i), element k of lane'??
    // Simpler: rearrange iv into a flat per-dim array indexed consistently.
    // Lane l fp32 holds dims {4l..4l+3, 4l+32..., 4l+64..., 4l+96...}
    // Lane l fp16 holds dims {8l..8l+7, 8l+64..8l+71}
    // These differ! Need matching dim sets for the dot product. Fix: gather
    // emb with the fp16-dim pattern: dims 8l+64i..+7 = two float4s per chunk:
    //   float4 at byte 32l + 256i      -> dims 8l+64i .. +3
    //   float4 at byte 32l + 256i + 16 -> dims 8l+64i+4 .. +7
    // But 32l+256i for l=0..7 covers bytes {0..255} stride 32: each 128B line
    // touched by 4 lanes x 2 float4 = still full-line coalesced per request
    // pair. Re-load with that pattern instead:
    float ivf[16];
#pragma unroll
    for (int i = 0; i < 2; i++) {
        float4 p0 = __ldg(reinterpret_cast<const float4*>(e_b + t_off + lane * 32u + 256u * i));
        float4 p1 = __ldg(reinterpret_cast<const float4*>(e_b + t_off + lane * 32u + 256u * i + 16u));
        ivf[i * 8 + 0] = p0.x; ivf[i * 8 + 1] = p0.y;
        ivf[i * 8 + 2] = p0.z; ivf[i * 8 + 3] = p0.w;
        ivf[i * 8 + 4] = p1.x; ivf[i * 8 + 5] = p1.y;
        ivf[i * 8 + 6] = p1.z; ivf[i * 8 + 7] = p1.w;
    }
    (void)iv;

    // double-buffered walk over the 6 fp16 w rows
    uint4 cur[2], nxt[2];
#pragma unroll
    for (int i = 0; i < 2; i++)
        cur[i] = ldg_u4_hint(w_b + roff[0] + lane16 + 128u * i, pol_last);

    float s[1 + KNEG];
#pragma unroll
    for (int j = 0; j < 1 + KNEG; j++) {
        if (j < KNEG) {
#pragma unroll
            for (int i = 0; i < 2; i++)
                nxt[i] = ldg_u4_hint(w_b + roff[j + 1] + lane16 + 128u * i, pol_last);
        }
        float acc = 0.f;
#pragma unroll
        for (int i = 0; i < 2; i++) {
            const __half2* h = reinterpret_cast<const __half2*>(&cur[i]);
#pragma unroll
            for (int q = 0; q < 4; q++) {
                float2 f = __half22float2(h[q]);
                acc = fmaf(ivf[i * 8 + q * 2 + 0], f.x, acc);
                acc = fmaf(ivf[i * 8 + q * 2 + 1], f.y, acc);
            }
        }
        s[j] = acc;
        if (j < KNEG) {
            cur[0] = nxt[0];
            cur[1] = nxt[1];
        }
    }

    // 3-stage butterfly: all lanes end with all 6 sums
#pragma unroll
    for (int j = 0; j < 1 + KNEG; j++) {
#pragma unroll
        for (int off = LPP / 2; off > 0; off >>= 1)
            s[j] += __shfl_xor_sync(gmask, s[j], off, LPP);
    }

    // Parallel epilogue: lanes 0..5 each evaluate one log-sigmoid term
    float x = (lane == 0) ? s[0] : -s[lane < 6 ? lane : 0];
    float term = log_sigmoid(x);
    if (lane >= 6) term = 0.f;
#pragma unroll
    for (int off = LPP / 2; off > 0; off >>= 1)
        term += __shfl_xor_sync(gmask, term, off, LPP);

    if (lane == 0)
        __stwt(out + pair, -term);
}

extern "C" void kernel_launch(void* const* d_in, const int* in_sizes, int n_in,
                              void* d_out, int out_size) {
    const float* emb     = (const float*)d_in[0];
    const float* out_w   = (const float*)d_in[1];
    const int*   tgt_ids = (const int*)d_in[2];
    const int*   ctx_ids = (const int*)d_in[3];
    const int*   neg_ids = (const int*)d_in[4];
    float*       out     = (float*)d_out;

    const int n_w = in_sizes[1];              // V * D elements (out_w)
    const int N   = in_sizes[2];              // number of pairs

    // K1: convert out_w -> fp16 (8 elems/thread, R10-proven form)
    {
        const int threads = 256;
        const int blocks = (n_w / 8 + threads - 1) / threads;
        convert_w_kernel<<<blocks, threads>>>(out_w, n_w);
    }

    // K2: main pass
    {
        const int threads = 256;               // 32 pairs per block
        const int pairs_per_block = threads / LPP;
        const int blocks = (N + pairs_per_block - 1) / pairs_per_block;
        sgns_loss_kernel<<<blocks, threads>>>(emb, tgt_ids, ctx_ids, neg_ids, out, N);
    }
}